// round 2
// baseline (speedup 1.0000x reference)
#include <cuda_runtime.h>
#include <cstdint>

// Problem constants (fixed shapes for this problem instance)
#define B_ 32
#define T_ 10
#define P_ 25
#define H_ 100
#define W_ 100

#define OUT_ELEMS (B_ * T_ * H_ * W_ * P_)   // 80,000,000 floats = 320 MB

// ---------------------------------------------------------------------------
// Scatter 1.0f for each in-bounds point. One thread per (b, t, p).
// Each point owns a distinct innermost-p slot -> no collisions -> plain store
// is exactly the reference's scatter-max. Truncating (int) cast matches
// jnp astype(int32).
// Launch config: 64-thread blocks so the 8000 threads spread across ~125 SMs,
// one latency chain (5 loads + 1 scattered store) per SM.
// ---------------------------------------------------------------------------
__global__ void __launch_bounds__(64) scatter_points_kernel(
        const float* __restrict__ x,
        const float* __restrict__ resolution,
        const float* __restrict__ origin,
        float* __restrict__ out) {
    int i = blockIdx.x * blockDim.x + threadIdx.x;  // 0 .. B*T*P-1
    if (i >= B_ * T_ * P_) return;

    int p  = i % P_;
    int bt = i / P_;          // b*T + t

    // x layout: [B, T, 2P]; point p is (x, y) at (2p, 2p+1)
    const float2 pxy = *(const float2*)(x + (size_t)bt * (2 * P_) + 2 * p);

    // resolution/origin layout: [B, T, 2]
    const float2 res = *(const float2*)(resolution + 2 * bt);
    const float2 org = *(const float2*)(origin + 2 * bt);

    int row = (int)(pxy.y / res.x + org.x);  // truncating cast == astype(int32)
    int col = (int)(pxy.x / res.y + org.y);

    if (row >= 0 && row < H_ && col >= 0 && col < W_) {
        size_t idx = ((((size_t)bt * H_ + row) * W_) + col) * P_ + p;
        out[idx] = 1.0f;
    }
}

extern "C" void kernel_launch(void* const* d_in, const int* in_sizes, int n_in,
                              void* d_out, int out_size) {
    const float* x          = (const float*)d_in[0];
    const float* resolution = (const float*)d_in[1];
    const float* origin     = (const float*)d_in[2];
    float* out = (float*)d_out;

    // 1) zero-fill 320MB of output via the driver memset path
    //    (captures as a native memset node; async, allocation-free)
    cudaMemsetAsync(out, 0, (size_t)OUT_ELEMS * sizeof(float), 0);

    // 2) scatter 8000 points (same stream -> ordered after the memset)
    {
        const int total   = B_ * T_ * P_;  // 8000
        const int threads = 64;
        const int blocks  = (total + threads - 1) / threads;  // 125
        scatter_points_kernel<<<blocks, threads>>>(x, resolution, origin, out);
    }
}

// round 5
// speedup vs baseline: 1.4517x; 1.4517x over previous
#include <cuda_runtime.h>
#include <cstdint>

// Problem constants (fixed shapes for this problem instance)
#define B_ 32
#define T_ 10
#define P_ 25
#define H_ 100
#define W_ 100

#define OUT_ELEMS (B_ * T_ * H_ * W_ * P_)   // 80,000,000 floats = 320 MB
#define OUT_VEC4  (OUT_ELEMS / 4)            // 20,000,000 float4s

#define FILL_BLOCKS  1184                    // 148 SMs * 8
#define FILL_THREADS 1024

// ---------------------------------------------------------------------------
// Kernel 1: zero-fill with grid-stride, 4-way unrolled streaming STG.128.
// Each iteration issues 4 independent 16B stores (coalesced across the warp),
// giving store-level MLP per thread instead of relying on warp count alone.
// __stcs = streaming hint: don't keep 320MB of zeros resident in L2.
// ---------------------------------------------------------------------------
__global__ void __launch_bounds__(FILL_THREADS) zero_fill_kernel(float4* __restrict__ out) {
    const float4 z = make_float4(0.f, 0.f, 0.f, 0.f);
    const size_t stride = (size_t)FILL_BLOCKS * FILL_THREADS;      // 1,212,416
    size_t i = (size_t)blockIdx.x * FILL_THREADS + threadIdx.x;

    // Main loop: 4 independent stores per iteration.
    size_t end4 = (size_t)OUT_VEC4 - 3 * stride;
    for (; i < end4; i += 4 * stride) {
        __stcs(&out[i],              z);
        __stcs(&out[i +     stride], z);
        __stcs(&out[i + 2 * stride], z);
        __stcs(&out[i + 3 * stride], z);
    }
    // Remainder
    for (; i < (size_t)OUT_VEC4; i += stride) {
        __stcs(&out[i], z);
    }
}

// ---------------------------------------------------------------------------
// Kernel 2: scatter 1.0f for each in-bounds point. One thread per (b, t, p).
// Each point owns a distinct innermost-p slot -> no collisions -> plain store
// is exactly the reference's scatter-max. Truncating (int) cast matches
// jnp astype(int32).
// ---------------------------------------------------------------------------
__global__ void __launch_bounds__(64) scatter_points_kernel(
        const float* __restrict__ x,
        const float* __restrict__ resolution,
        const float* __restrict__ origin,
        float* __restrict__ out) {
    int i = blockIdx.x * blockDim.x + threadIdx.x;  // 0 .. B*T*P-1
    if (i >= B_ * T_ * P_) return;

    int p  = i % P_;
    int bt = i / P_;          // b*T + t

    // x layout: [B, T, 2P]; point p is (x, y) at (2p, 2p+1)
    const float2 pxy = *(const float2*)(x + (size_t)bt * (2 * P_) + 2 * p);

    // resolution/origin layout: [B, T, 2]
    const float2 res = *(const float2*)(resolution + 2 * bt);
    const float2 org = *(const float2*)(origin + 2 * bt);

    int row = (int)(pxy.y / res.x + org.x);  // truncating cast == astype(int32)
    int col = (int)(pxy.x / res.y + org.y);

    if (row >= 0 && row < H_ && col >= 0 && col < W_) {
        size_t idx = ((((size_t)bt * H_ + row) * W_) + col) * P_ + p;
        out[idx] = 1.0f;
    }
}

extern "C" void kernel_launch(void* const* d_in, const int* in_sizes, int n_in,
                              void* d_out, int out_size) {
    const float* x          = (const float*)d_in[0];
    const float* resolution = (const float*)d_in[1];
    const float* origin     = (const float*)d_in[2];
    float* out = (float*)d_out;

    // 1) zero-fill 320MB of output
    zero_fill_kernel<<<FILL_BLOCKS, FILL_THREADS>>>((float4*)out);

    // 2) scatter 8000 points (same stream -> ordered after the fill)
    {
        const int total   = B_ * T_ * P_;  // 8000
        const int threads = 64;
        const int blocks  = (total + threads - 1) / threads;  // 125
        scatter_points_kernel<<<blocks, threads>>>(x, resolution, origin, out);
    }
}

// round 6
// speedup vs baseline: 1.4635x; 1.0081x over previous
#include <cuda_runtime.h>
#include <cstdint>

// Problem constants (fixed shapes for this problem instance)
#define B_ 32
#define T_ 10
#define P_ 25
#define H_ 100
#define W_ 100

#define OUT_ELEMS (B_ * T_ * H_ * W_ * P_)   // 80,000,000 floats = 320 MB
#define OUT_VEC4  (OUT_ELEMS / 4)            // 20,000,000 float4s

#define FILL_BLOCKS  1184                    // 148 SMs * 8
#define FILL_THREADS 1024

// ---------------------------------------------------------------------------
// Kernel 1: zero-fill with grid-stride, 8-way unrolled streaming STG.128.
// 6.7 TB/s measured in R5 with 4-way; 8-way gives each warp more outstanding
// stores. __stcs: don't keep 320MB of zeros resident in L2.
// ---------------------------------------------------------------------------
__global__ void __launch_bounds__(FILL_THREADS) zero_fill_kernel(float4* __restrict__ out) {
    const float4 z = make_float4(0.f, 0.f, 0.f, 0.f);
    const size_t stride = (size_t)FILL_BLOCKS * FILL_THREADS;      // 1,212,416
    size_t i = (size_t)blockIdx.x * FILL_THREADS + threadIdx.x;

    // Main loop: 8 independent stores per iteration.
    const size_t end8 = (size_t)OUT_VEC4 > 7 * stride ? (size_t)OUT_VEC4 - 7 * stride : 0;
    for (; i < end8; i += 8 * stride) {
        __stcs(&out[i],              z);
        __stcs(&out[i +     stride], z);
        __stcs(&out[i + 2 * stride], z);
        __stcs(&out[i + 3 * stride], z);
        __stcs(&out[i + 4 * stride], z);
        __stcs(&out[i + 5 * stride], z);
        __stcs(&out[i + 6 * stride], z);
        __stcs(&out[i + 7 * stride], z);
    }
    // Remainder
    for (; i < (size_t)OUT_VEC4; i += stride) {
        __stcs(&out[i], z);
    }
}

// ---------------------------------------------------------------------------
// Kernel 2: scatter 1.0f per in-bounds point, launched with programmatic
// stream serialization (PDL). Blocks start while the fill is still running:
// all loads + index math execute concurrently with the fill; the store is
// gated behind cudaGridDependencySynchronize(), which guarantees the fill's
// stores are visible. Each point owns a distinct innermost-p slot -> no
// collisions -> plain store == the reference's scatter-max. Truncating (int)
// cast matches jnp astype(int32).
// ---------------------------------------------------------------------------
__global__ void __launch_bounds__(64) scatter_points_kernel(
        const float* __restrict__ x,
        const float* __restrict__ resolution,
        const float* __restrict__ origin,
        float* __restrict__ out) {
    int i = blockIdx.x * blockDim.x + threadIdx.x;  // 0 .. B*T*P-1

    bool active = (i < B_ * T_ * P_);
    size_t idx = 0;
    bool write = false;

    if (active) {
        int p  = i % P_;
        int bt = i / P_;          // b*T + t

        // x layout: [B, T, 2P]; point p is (x, y) at (2p, 2p+1)
        const float2 pxy = *(const float2*)(x + (size_t)bt * (2 * P_) + 2 * p);

        // resolution/origin layout: [B, T, 2]
        const float2 res = *(const float2*)(resolution + 2 * bt);
        const float2 org = *(const float2*)(origin + 2 * bt);

        int row = (int)(pxy.y / res.x + org.x);  // truncating cast == astype(int32)
        int col = (int)(pxy.x / res.y + org.y);

        if (row >= 0 && row < H_ && col >= 0 && col < W_) {
            idx = ((((size_t)bt * H_ + row) * W_) + col) * P_ + p;
            write = true;
        }
    }

    // Wait for the upstream fill's stores to be visible, then commit.
    cudaGridDependencySynchronize();

    if (write) {
        out[idx] = 1.0f;
    }
}

extern "C" void kernel_launch(void* const* d_in, const int* in_sizes, int n_in,
                              void* d_out, int out_size) {
    const float* x          = (const float*)d_in[0];
    const float* resolution = (const float*)d_in[1];
    const float* origin     = (const float*)d_in[2];
    float* out = (float*)d_out;

    // 1) zero-fill 320MB of output
    zero_fill_kernel<<<FILL_BLOCKS, FILL_THREADS>>>((float4*)out);

    // 2) scatter 8000 points, overlapped with the fill via PDL.
    {
        const int total   = B_ * T_ * P_;  // 8000
        const int threads = 64;
        const int blocks  = (total + threads - 1) / threads;  // 125

        cudaLaunchConfig_t cfg = {};
        cfg.gridDim  = dim3(blocks);
        cfg.blockDim = dim3(threads);
        cfg.dynamicSmemBytes = 0;
        cfg.stream = 0;

        cudaLaunchAttribute attrs[1];
        attrs[0].id = cudaLaunchAttributeProgrammaticStreamSerialization;
        attrs[0].val.programmaticStreamSerializationAllowed = 1;
        cfg.attrs = attrs;
        cfg.numAttrs = 1;

        cudaLaunchKernelEx(&cfg, scatter_points_kernel, x, resolution, origin, out);
    }
}